// round 3
// baseline (speedup 1.0000x reference)
#include <cuda_runtime.h>
#include <math.h>

#define BATCH 2
#define SEQ   4096
#define DM    2048
#define DI    4096
#define NH    32
#define HD    128
#define DS    64
#define CONVD (DI + 2*DS)          /* 4224 */
#define DIP   (2*DI + 2*DS + NH)   /* 8352 */
#define OFF_DT (DI + CONVD)        /* 8320 */
#define CHUNK 256
#define NC    (SEQ/CHUNK)          /* 16 */
#define TOK   (BATCH*SEQ)          /* 8192 */

typedef unsigned long long u64;
union F4D2 { float4 f4; u64 d[2]; };

#define FMA2(acc, a, b) asm("fma.rn.f32x2 %0, %1, %2, %0;" : "+l"(acc) : "l"(a), "l"(b))

// ---------------- scratch (device globals; no allocation allowed) ----------------
__device__ float g_zxbcdt[(size_t)TOK*DIP];            // 274 MB
__device__ float g_dtsp[TOK*NH];
__device__ float g_dacs[BATCH*NH*NC*CHUNK];            // per-chunk cumsum of A*dt
__device__ float g_csum[BATCH*NH*NC];                  // chunk totals
__device__ float g_X[(size_t)BATCH*NC*NH*CHUNK*HD];    // x*dt, tiled   134 MB
__device__ float g_Bm[BATCH*NC*CHUNK*DS];
__device__ float g_Cm[BATCH*NC*CHUNK*DS];
__device__ float g_G[BATCH*NC*CHUNK*CHUNK];            // C @ B^T per (b,c)
__device__ float g_states[(size_t)BATCH*NC*NH*HD*DS];
__device__ float g_inter[(size_t)BATCH*NC*NH*HD*DS];
__device__ float g_y[(size_t)TOK*DI];                  // 134 MB
__device__ float g_yn[(size_t)TOK*DI];                 // 134 MB

// ---------------- K1/K9: SGEMM  C[M,N] = A[M,K] @ B[N,K]^T + bias[N] ----------------
// f32x2 packed-FMA version. 128x128x16 tile, 8x8/thread, double-buffered smem,
// A stored duplicated in shared so packed (a,a) pairs load as one LDS.128.
__global__ __launch_bounds__(256) void sgemm_nt(
    const float* __restrict__ A, const float* __restrict__ B,
    const float* __restrict__ bias, float* __restrict__ C,
    int M, int N, int K)
{
    __shared__ __align__(16) float As[2][16][256];   // duplicated A: [kk][2r]=[kk][2r+1]
    __shared__ __align__(16) float Bs[2][16][128];
    int tid = threadIdx.x;
    int tx = tid & 15, ty = tid >> 4;
    int m0 = blockIdx.y * 128, n0 = blockIdx.x * 128;

    int r0  = tid >> 2;            // 0..63
    int kk0 = (tid & 3) << 2;      // 0,4,8,12

    u64 acc[8][4];
#pragma unroll
    for (int i = 0; i < 8; i++)
#pragma unroll
        for (int p = 0; p < 4; p++) acc[i][p] = 0ULL;

    const float4 z4 = make_float4(0.f, 0.f, 0.f, 0.f);
    bool ok0 = (n0 + r0) < N;
    bool ok1 = (n0 + r0 + 64) < N;

    // initial prefetch (k0 = 0)
    float4 pa0 = *(const float4*)&A[(size_t)(m0 + r0) * K + kk0];
    float4 pa1 = *(const float4*)&A[(size_t)(m0 + r0 + 64) * K + kk0];
    float4 pb0 = ok0 ? *(const float4*)&B[(size_t)(n0 + r0) * K + kk0] : z4;
    float4 pb1 = ok1 ? *(const float4*)&B[(size_t)(n0 + r0 + 64) * K + kk0] : z4;

    int buf = 0;
    for (int k0 = 0; k0 < K; k0 += 16) {
        // ---- store prefetched regs into smem[buf] ----
        {
            float2 d;
            d.x = d.y = pa0.x; *(float2*)&As[buf][kk0 + 0][2 * r0] = d;
            d.x = d.y = pa0.y; *(float2*)&As[buf][kk0 + 1][2 * r0] = d;
            d.x = d.y = pa0.z; *(float2*)&As[buf][kk0 + 2][2 * r0] = d;
            d.x = d.y = pa0.w; *(float2*)&As[buf][kk0 + 3][2 * r0] = d;
            d.x = d.y = pa1.x; *(float2*)&As[buf][kk0 + 0][2 * (r0 + 64)] = d;
            d.x = d.y = pa1.y; *(float2*)&As[buf][kk0 + 1][2 * (r0 + 64)] = d;
            d.x = d.y = pa1.z; *(float2*)&As[buf][kk0 + 2][2 * (r0 + 64)] = d;
            d.x = d.y = pa1.w; *(float2*)&As[buf][kk0 + 3][2 * (r0 + 64)] = d;
            Bs[buf][kk0 + 0][r0] = pb0.x;
            Bs[buf][kk0 + 1][r0] = pb0.y;
            Bs[buf][kk0 + 2][r0] = pb0.z;
            Bs[buf][kk0 + 3][r0] = pb0.w;
            Bs[buf][kk0 + 0][r0 + 64] = pb1.x;
            Bs[buf][kk0 + 1][r0 + 64] = pb1.y;
            Bs[buf][kk0 + 2][r0 + 64] = pb1.z;
            Bs[buf][kk0 + 3][r0 + 64] = pb1.w;
        }
        __syncthreads();

        // ---- prefetch next k-tile into regs ----
        if (k0 + 16 < K) {
            int kn = k0 + 16 + kk0;
            pa0 = *(const float4*)&A[(size_t)(m0 + r0) * K + kn];
            pa1 = *(const float4*)&A[(size_t)(m0 + r0 + 64) * K + kn];
            pb0 = ok0 ? *(const float4*)&B[(size_t)(n0 + r0) * K + kn] : z4;
            pb1 = ok1 ? *(const float4*)&B[(size_t)(n0 + r0 + 64) * K + kn] : z4;
        }

        // ---- compute on smem[buf] ----
#pragma unroll
        for (int kk = 0; kk < 16; kk++) {
            F4D2 av[4], bv[2];
#pragma unroll
            for (int q = 0; q < 4; q++)
                av[q].f4 = *(const float4*)&As[buf][kk][ty * 16 + q * 4];
            bv[0].f4 = *(const float4*)&Bs[buf][kk][tx * 8];
            bv[1].f4 = *(const float4*)&Bs[buf][kk][tx * 8 + 4];
#pragma unroll
            for (int i = 0; i < 8; i++)
#pragma unroll
                for (int p = 0; p < 4; p++)
                    FMA2(acc[i][p], av[i >> 1].d[i & 1], bv[p >> 1].d[p & 1]);
        }
        buf ^= 1;
    }

#pragma unroll
    for (int i = 0; i < 8; i++) {
        int m = m0 + ty * 8 + i;
        float cf[8];
#pragma unroll
        for (int p = 0; p < 4; p++) {
            u64 v = acc[i][p];
            cf[2 * p + 0] = __int_as_float((int)(v & 0xffffffffULL));
            cf[2 * p + 1] = __int_as_float((int)(v >> 32));
        }
#pragma unroll
        for (int j = 0; j < 8; j += 4) {
            int n = n0 + tx * 8 + j;
            if (n + 3 < N) {
                float4 v;
                v.x = cf[j + 0] + bias[n + 0];
                v.y = cf[j + 1] + bias[n + 1];
                v.z = cf[j + 2] + bias[n + 2];
                v.w = cf[j + 3] + bias[n + 3];
                *(float4*)&C[(size_t)m * N + n] = v;
            } else {
                for (int q = 0; q < 4; q++)
                    if (n + q < N) C[(size_t)m * N + n + q] = cf[j + q] + bias[n + q];
            }
        }
    }
}

// ---------------- K2: dt softplus + per-chunk inclusive cumsum of A*dt ----------------
__global__ __launch_bounds__(256) void dt_scan_kernel(
    const float* __restrict__ dt_bias, const float* __restrict__ A_log)
{
    int blk = blockIdx.x;            // (b*NH + h)*NC + c
    int c = blk % NC; int bh = blk / NC;
    int h = bh % NH;  int b = bh / NH;
    int t = threadIdx.x;
    int l = c * CHUNK + t;

    float x = g_zxbcdt[(size_t)(b * SEQ + l) * DIP + OFF_DT + h] + dt_bias[h];
    float sp = (x > 20.f) ? x : log1pf(expf(x));
    g_dtsp[(b * SEQ + l) * NH + h] = sp;
    float da = -expf(A_log[h]) * sp;

    __shared__ float s[CHUNK];
    s[t] = da;
    __syncthreads();
    for (int off = 1; off < CHUNK; off <<= 1) {
        float v = (t >= off) ? s[t - off] : 0.f;
        __syncthreads();
        s[t] += v;
        __syncthreads();
    }
    int base = ((b * NH + h) * NC + c) * CHUNK;
    g_dacs[base + t] = s[t];
    if (t == CHUNK - 1) g_csum[(b * NH + h) * NC + c] = s[t];
}

// ---------------- K3: causal depthwise conv4 + SiLU + scatter ----------------
__global__ __launch_bounds__(256) void conv_kernel(
    const float* __restrict__ conv_w, const float* __restrict__ conv_b)
{
    int tok = blockIdx.x;                       // 0..TOK-1
    int ch = blockIdx.y * 256 + threadIdx.x;
    if (ch >= CONVD) return;
    int b = tok / SEQ, l = tok % SEQ;

    const float* w = conv_w + ch * 4;
    float acc = conv_b[ch];
#pragma unroll
    for (int j = 0; j < 4; j++) {
        int ls = l - 3 + j;
        if (ls >= 0)
            acc += w[j] * g_zxbcdt[(size_t)(b * SEQ + ls) * DIP + DI + ch];
    }
    float v = acc / (1.f + __expf(-acc));       // silu

    int c = l / CHUNK, t = l % CHUNK;
    if (ch < DI) {
        int h = ch >> 7, p = ch & 127;
        float dt = g_dtsp[(b * SEQ + l) * NH + h];
        g_X[(size_t)(((b * NC + c) * NH + h) * CHUNK + t) * HD + p] = v * dt;
    } else if (ch < DI + DS) {
        g_Bm[((b * NC + c) * CHUNK + t) * DS + (ch - DI)] = v;
    } else {
        g_Cm[((b * NC + c) * CHUNK + t) * DS + (ch - DI - DS)] = v;
    }
}

// ---------------- K4: G[l,s] = sum_n C[l,n] B[s,n] per (b,c) ----------------
__global__ __launch_bounds__(256) void bc_gemm_kernel()
{
    int bc = blockIdx.y;                         // 0..31
    int tile = blockIdx.x;                       // 0..15
    int l0 = (tile >> 2) * 64, s0 = (tile & 3) * 64;
    __shared__ float Cs[64][65];
    __shared__ float Bs[64][65];
    int tid = threadIdx.x;
    const float* Cb = g_Cm + (size_t)bc * CHUNK * DS;
    const float* Bb = g_Bm + (size_t)bc * CHUNK * DS;

#pragma unroll
    for (int u = 0; u < 4; u++) {
        int e = tid + u * 256;                   // 1024 float4
        int r = e >> 4, cv = (e & 15) << 2;
        float4 vc = *(const float4*)&Cb[(l0 + r) * DS + cv];
        Cs[r][cv + 0] = vc.x; Cs[r][cv + 1] = vc.y; Cs[r][cv + 2] = vc.z; Cs[r][cv + 3] = vc.w;
        float4 vb = *(const float4*)&Bb[(s0 + r) * DS + cv];
        Bs[r][cv + 0] = vb.x; Bs[r][cv + 1] = vb.y; Bs[r][cv + 2] = vb.z; Bs[r][cv + 3] = vb.w;
    }
    __syncthreads();

    int sq = tid & 15, lq = tid >> 4;
    float acc[4][4];
#pragma unroll
    for (int i = 0; i < 4; i++)
#pragma unroll
        for (int j = 0; j < 4; j++) acc[i][j] = 0.f;

#pragma unroll 8
    for (int n = 0; n < 64; n++) {
        float a[4], bb[4];
#pragma unroll
        for (int i = 0; i < 4; i++) a[i] = Cs[lq * 4 + i][n];
#pragma unroll
        for (int j = 0; j < 4; j++) bb[j] = Bs[sq * 4 + j][n];
#pragma unroll
        for (int i = 0; i < 4; i++)
#pragma unroll
            for (int j = 0; j < 4; j++) acc[i][j] = fmaf(a[i], bb[j], acc[i][j]);
    }
    float* Gout = g_G + (size_t)bc * CHUNK * CHUNK;
#pragma unroll
    for (int i = 0; i < 4; i++) {
        float4 v = make_float4(acc[i][0], acc[i][1], acc[i][2], acc[i][3]);
        *(float4*)&Gout[(l0 + lq * 4 + i) * CHUNK + s0 + sq * 4] = v;
    }
}

// ---------------- K5: Y_diag = (G .* L) @ X per (b,c,h), f32x2 ----------------
__global__ __launch_bounds__(512) void ydiag_kernel()
{
    int blk = blockIdx.x;                        // ((b*NC+c)*NH + h)
    int h = blk % NH; int bc = blk / NH;
    int c = bc % NC;  int b = bc / NC;

    __shared__ __align__(16) float Ms[16][512];  // duplicated along row index
    __shared__ __align__(16) float Xs[16][128];
    __shared__ float acs[CHUNK];
    int tid = threadIdx.x;
    if (tid < 256) acs[tid] = g_dacs[((b * NH + h) * NC + c) * CHUNK + tid];
    __syncthreads();

    const float* Gb = g_G + (size_t)bc * CHUNK * CHUNK;
    const float* Xb = g_X + (size_t)blk * CHUNK * HD;

    u64 acc[8][4];
#pragma unroll
    for (int i = 0; i < 8; i++)
#pragma unroll
        for (int p = 0; p < 4; p++) acc[i][p] = 0ULL;

    int tx = tid & 15, ty = tid >> 4;            // ty 0..31 (l), tx 0..15 (p)

    for (int s0 = 0; s0 < CHUNK; s0 += 16) {
        {   // X tile: 16 x 128, 512 float4, one per thread
            int r = tid >> 5, cv = (tid & 31) << 2;
            float4 v = *(const float4*)&Xb[(s0 + r) * HD + cv];
            *(float4*)&Xs[r][cv] = v;
        }
#pragma unroll
        for (int u = 0; u < 2; u++) {            // M tile: 256 x 16 transposed, duplicated
            int e = tid * 2 + u;
            int r = e >> 2;                      // l (0..255)
            int sv = (e & 3) << 2;               // s offset
            float4 g4 = *(const float4*)&Gb[r * CHUNK + s0 + sv];
            float al = acs[r];
            int sg = s0 + sv;
            float m0v = (sg + 0 <= r) ? g4.x * __expf(al - acs[sg + 0]) : 0.f;
            float m1v = (sg + 1 <= r) ? g4.y * __expf(al - acs[sg + 1]) : 0.f;
            float m2v = (sg + 2 <= r) ? g4.z * __expf(al - acs[sg + 2]) : 0.f;
            float m3v = (sg + 3 <= r) ? g4.w * __expf(al - acs[sg + 3]) : 0.f;
            float2 d;
            d.x = d.y = m0v; *(float2*)&Ms[sv + 0][2 * r] = d;
            d.x = d.y = m1v; *(float2*)&Ms[sv + 1][2 * r] = d;
            d.x = d.y = m2v; *(float2*)&Ms[sv + 2][2 * r] = d;
            d.x = d.y = m3v; *(float2*)&Ms[sv + 3][2 * r] = d;
        }
        __syncthreads();
#pragma unroll
        for (int kk = 0; kk < 16; kk++) {
            F4D2 av[4], bv[2];
#pragma unroll
            for (int q = 0; q < 4; q++)
                av[q].f4 = *(const float4*)&Ms[kk][ty * 16 + q * 4];
            bv[0].f4 = *(const float4*)&Xs[kk][tx * 8];
            bv[1].f4 = *(const float4*)&Xs[kk][tx * 8 + 4];
#pragma unroll
            for (int i = 0; i < 8; i++)
#pragma unroll
                for (int p = 0; p < 4; p++)
                    FMA2(acc[i][p], av[i >> 1].d[i & 1], bv[p >> 1].d[p & 1]);
        }
        __syncthreads();
    }

#pragma unroll
    for (int i = 0; i < 8; i++) {
        int l = ty * 8 + i;
        float* out = g_y + (size_t)(b * SEQ + c * CHUNK + l) * DI + h * HD;
        float cf[8];
#pragma unroll
        for (int p = 0; p < 4; p++) {
            u64 v = acc[i][p];
            cf[2 * p + 0] = __int_as_float((int)(v & 0xffffffffULL));
            cf[2 * p + 1] = __int_as_float((int)(v >> 32));
        }
#pragma unroll
        for (int j = 0; j < 8; j += 4) {
            float4 v = make_float4(cf[j], cf[j + 1], cf[j + 2], cf[j + 3]);
            *(float4*)&out[tx * 8 + j] = v;
        }
    }
}

// ---------------- K5b: local states[p,n] = sum_l X[l,p]*decay[l]*B[l,n] ----------------
__global__ __launch_bounds__(256) void states_kernel()
{
    int blk = blockIdx.x;
    int h = blk % NH; int bc = blk / NH;
    int c = bc % NC;  int b = bc / NC;

    __shared__ __align__(16) float Xs[32][128];
    __shared__ __align__(16) float Bs[32][64];
    __shared__ float ws[32];
    __shared__ float acs[CHUNK];
    int tid = threadIdx.x;
    if (tid < 256) acs[tid] = g_dacs[((b * NH + h) * NC + c) * CHUNK + tid];
    __syncthreads();
    float alast = acs[CHUNK - 1];

    const float* Xb = g_X + (size_t)blk * CHUNK * HD;
    const float* Bb = g_Bm + (size_t)bc * CHUNK * DS;

    int nq = tid & 7, pq = tid >> 3;             // p0 = pq*4 (0..124), n0 = nq*8
    float acc[4][8];
#pragma unroll
    for (int i = 0; i < 4; i++)
#pragma unroll
        for (int j = 0; j < 8; j++) acc[i][j] = 0.f;

    for (int l0 = 0; l0 < CHUNK; l0 += 32) {
#pragma unroll
        for (int u = 0; u < 4; u++) {            // X: 32x128 = 1024 float4
            int e = tid + u * 256;
            int r = e >> 5, cv = (e & 31) << 2;
            *(float4*)&Xs[r][cv] = *(const float4*)&Xb[(l0 + r) * HD + cv];
        }
#pragma unroll
        for (int u = 0; u < 2; u++) {            // B: 32x64 = 512 float4
            int e = tid + u * 256;
            int r = e >> 4, cv = (e & 15) << 2;
            *(float4*)&Bs[r][cv] = *(const float4*)&Bb[(l0 + r) * DS + cv];
        }
        if (tid < 32) ws[tid] = __expf(alast - acs[l0 + tid]);
        __syncthreads();
#pragma unroll
        for (int lt = 0; lt < 32; lt++) {
            float w = ws[lt];
            float a[4];
#pragma unroll
            for (int i = 0; i < 4; i++) a[i] = Xs[lt][pq * 4 + i] * w;
            float bb[8];
            *(float4*)&bb[0] = *(float4*)&Bs[lt][nq * 8];
            *(float4*)&bb[4] = *(float4*)&Bs[lt][nq * 8 + 4];
#pragma unroll
            for (int i = 0; i < 4; i++)
#pragma unroll
                for (int j = 0; j < 8; j++)
                    acc[i][j] = fmaf(a[i], bb[j], acc[i][j]);
        }
        __syncthreads();
    }
    float* So = g_states + (size_t)blk * HD * DS;
#pragma unroll
    for (int i = 0; i < 4; i++) {
#pragma unroll
        for (int j = 0; j < 8; j += 4) {
            float4 v = make_float4(acc[i][j], acc[i][j + 1], acc[i][j + 2], acc[i][j + 3]);
            *(float4*)&So[(pq * 4 + i) * DS + nq * 8 + j] = v;
        }
    }
}

// ---------------- K6: inter-chunk scan (16 sequential steps) ----------------
__global__ __launch_bounds__(256) void scan_kernel()
{
    int bh = blockIdx.x;                         // b*NH + h
    int b = bh / NH, h = bh % NH;
    int tid = threadIdx.x;
    float S[32];
#pragma unroll
    for (int k = 0; k < 32; k++) S[k] = 0.f;
    for (int c = 0; c < NC; c++) {
        float dec = __expf(g_csum[bh * NC + c]);
        size_t base = (size_t)((b * NC + c) * NH + h) * HD * DS;
#pragma unroll
        for (int k = 0; k < 32; k++) {
            int e = tid + k * 256;
            g_inter[base + e] = S[k];
            S[k] = S[k] * dec + g_states[base + e];
        }
    }
}

// ---------------- K7: Y_off + combine + silu(z) gate ----------------
__global__ __launch_bounds__(256) void yoff_kernel()
{
    int blk = blockIdx.x;
    int h = blk % NH; int bc = blk / NH;
    int c = bc % NC;  int b = bc / NC;

    __shared__ float Is[HD][DS + 1];             // inter, padded
    __shared__ float Cs[64][DS + 1];
    __shared__ float acs[CHUNK];
    int tid = threadIdx.x;
    if (tid < 256) acs[tid] = g_dacs[((b * NH + h) * NC + c) * CHUNK + tid];

    const float* Ib = g_inter + (size_t)blk * HD * DS;
#pragma unroll
    for (int u = 0; u < 8; u++) {                // 128x64 = 2048 float4
        int e = tid + u * 256;
        int r = e >> 4, cv = (e & 15) << 2;
        float4 v = *(const float4*)&Ib[r * DS + cv];
        Is[r][cv + 0] = v.x; Is[r][cv + 1] = v.y; Is[r][cv + 2] = v.z; Is[r][cv + 3] = v.w;
    }

    int tq = tid & 7, pq = tid >> 3;             // tq: t sub-lane, pq: p0 = pq*4
    const float* Cb = g_Cm + (size_t)bc * CHUNK * DS;

    for (int tg = 0; tg < 4; tg++) {
        __syncthreads();                          // protect Is (first iter) / Cs reuse
#pragma unroll
        for (int u = 0; u < 4; u++) {             // C tile 64x64 = 1024 float4
            int e = tid + u * 256;
            int r = e >> 4, cv = (e & 15) << 2;
            float4 v = *(const float4*)&Cb[(tg * 64 + r) * DS + cv];
            Cs[r][cv + 0] = v.x; Cs[r][cv + 1] = v.y; Cs[r][cv + 2] = v.z; Cs[r][cv + 3] = v.w;
        }
        __syncthreads();

        float acc[8][4];
#pragma unroll
        for (int k = 0; k < 8; k++)
#pragma unroll
            for (int i = 0; i < 4; i++) acc[k][i] = 0.f;

#pragma unroll 4
        for (int n = 0; n < DS; n++) {
            float iv[4];
#pragma unroll
            for (int i = 0; i < 4; i++) iv[i] = Is[pq * 4 + i][n];
#pragma unroll
            for (int k = 0; k < 8; k++) {
                float cv = Cs[k * 8 + tq][n];
#pragma unroll
                for (int i = 0; i < 4; i++)
                    acc[k][i] = fmaf(cv, iv[i], acc[k][i]);
            }
        }

#pragma unroll
        for (int k = 0; k < 8; k++) {
            int t = tg * 64 + k * 8 + tq;
            float ea = __expf(acs[t]);
            int gl = c * CHUNK + t;
            size_t yidx = (size_t)(b * SEQ + gl) * DI + h * HD + pq * 4;
            size_t zidx = (size_t)(b * SEQ + gl) * DIP + h * HD + pq * 4;
            float4 yd = *(float4*)&g_y[yidx];
            float4 z  = *(const float4*)&g_zxbcdt[zidx];
            float4 o;
            o.x = (yd.x + ea * acc[k][0]) * z.x / (1.f + __expf(-z.x));
            o.y = (yd.y + ea * acc[k][1]) * z.y / (1.f + __expf(-z.y));
            o.z = (yd.z + ea * acc[k][2]) * z.z / (1.f + __expf(-z.z));
            o.w = (yd.w + ea * acc[k][3]) * z.w / (1.f + __expf(-z.w));
            *(float4*)&g_y[yidx] = o;
        }
    }
}

// ---------------- K8: layernorm over 4096 ----------------
__global__ __launch_bounds__(256) void ln_kernel(
    const float* __restrict__ ln_w, const float* __restrict__ ln_b)
{
    int tok = blockIdx.x;
    const float* y = g_y + (size_t)tok * DI;
    float* o = g_yn + (size_t)tok * DI;
    int tid = threadIdx.x;

    float v[16];
    float s = 0.f, ss = 0.f;
#pragma unroll
    for (int u = 0; u < 4; u++) {
        float4 x = *(const float4*)&y[tid * 4 + u * 1024];
        v[u * 4 + 0] = x.x; v[u * 4 + 1] = x.y; v[u * 4 + 2] = x.z; v[u * 4 + 3] = x.w;
        s += x.x + x.y + x.z + x.w;
        ss += x.x * x.x + x.y * x.y + x.z * x.z + x.w * x.w;
    }
#pragma unroll
    for (int off = 16; off; off >>= 1) {
        s  += __shfl_xor_sync(0xFFFFFFFFu, s, off);
        ss += __shfl_xor_sync(0xFFFFFFFFu, ss, off);
    }
    __shared__ float rs[8], rss[8];
    int warp = tid >> 5, lane = tid & 31;
    if (lane == 0) { rs[warp] = s; rss[warp] = ss; }
    __syncthreads();
    s = 0.f; ss = 0.f;
#pragma unroll
    for (int w = 0; w < 8; w++) { s += rs[w]; ss += rss[w]; }
    float mu = s * (1.f / DI);
    float var = ss * (1.f / DI) - mu * mu;
    float rstd = rsqrtf(var + 1e-5f);
#pragma unroll
    for (int u = 0; u < 4; u++) {
        int idx = tid * 4 + u * 1024;
        float4 w4 = *(const float4*)&ln_w[idx];
        float4 b4 = *(const float4*)&ln_b[idx];
        float4 ov;
        ov.x = (v[u * 4 + 0] - mu) * rstd * w4.x + b4.x;
        ov.y = (v[u * 4 + 1] - mu) * rstd * w4.y + b4.y;
        ov.z = (v[u * 4 + 2] - mu) * rstd * w4.z + b4.z;
        ov.w = (v[u * 4 + 3] - mu) * rstd * w4.w + b4.w;
        *(float4*)&o[idx] = ov;
    }
}

// ---------------- launch ----------------
extern "C" void kernel_launch(void* const* d_in, const int* in_sizes, int n_in,
                              void* d_out, int out_size)
{
    const float* u          = (const float*)d_in[0];
    const float* in_proj_w  = (const float*)d_in[1];
    const float* in_proj_b  = (const float*)d_in[2];
    const float* conv_w     = (const float*)d_in[3];
    const float* conv_b     = (const float*)d_in[4];
    const float* dt_bias    = (const float*)d_in[5];
    const float* A_log      = (const float*)d_in[6];
    const float* ln_w       = (const float*)d_in[7];
    const float* ln_b       = (const float*)d_in[8];
    const float* out_proj_w = (const float*)d_in[9];
    const float* out_proj_b = (const float*)d_in[10];
    float* out = (float*)d_out;

    float* zx; cudaGetSymbolAddress((void**)&zx, g_zxbcdt);
    float* yn; cudaGetSymbolAddress((void**)&yn, g_yn);

    // K1: in_proj GEMM  (8192 x 8352 x 2048)
    sgemm_nt<<<dim3((DIP + 127) / 128, TOK / 128), 256>>>(
        u, in_proj_w, in_proj_b, zx, TOK, DIP, DM);
    // K2: dt softplus + per-chunk cumsum
    dt_scan_kernel<<<BATCH * NH * NC, CHUNK>>>(dt_bias, A_log);
    // K3: conv + silu + scatter
    conv_kernel<<<dim3(TOK, (CONVD + 255) / 256), 256>>>(conv_w, conv_b);
    // K4: G = C B^T per (b,c)
    bc_gemm_kernel<<<dim3(16, BATCH * NC), 256>>>();
    // K5: Y_diag
    ydiag_kernel<<<BATCH * NC * NH, 512>>>();
    // K5b: local chunk states
    states_kernel<<<BATCH * NC * NH, 256>>>();
    // K6: inter-chunk scan
    scan_kernel<<<BATCH * NH, 256>>>();
    // K7: Y_off + gate
    yoff_kernel<<<BATCH * NC * NH, 256>>>();
    // K8: layernorm
    ln_kernel<<<TOK, 256>>>(ln_w, ln_b);
    // K9: out_proj GEMM (8192 x 2048 x 4096)
    sgemm_nt<<<dim3(DM / 128, TOK / 128), 256>>>(
        yn, out_proj_w, out_proj_b, out, TOK, DM, DI);
}

// round 6
// speedup vs baseline: 4.4700x; 4.4700x over previous
#include <cuda_runtime.h>
#include <cuda_bf16.h>
#include <math.h>
#include <stdint.h>

#define BATCH 2
#define SEQ   4096
#define DM    2048
#define DI    4096
#define NH    32
#define HD    128
#define DS    64
#define CONVD (DI + 2*DS)          /* 4224 */
#define DIP   (2*DI + 2*DS + NH)   /* 8352 */
#define OFF_DT (DI + CONVD)        /* 8320 */
#define CHUNK 256
#define NC    (SEQ/CHUNK)          /* 16 */
#define TOK   (BATCH*SEQ)          /* 8192 */

// ---------------- scratch (device globals; no allocation allowed) ----------------
__device__ float g_zxbcdt[(size_t)TOK*DIP];
__device__ float g_dtsp[TOK*NH];
__device__ float g_dacs[BATCH*NH*NC*CHUNK];
__device__ float g_csum[BATCH*NH*NC];
__device__ float g_X[(size_t)BATCH*NC*NH*CHUNK*HD];
__device__ float g_Bm[BATCH*NC*CHUNK*DS];
__device__ float g_Cm[BATCH*NC*CHUNK*DS];
__device__ float g_G[BATCH*NC*CHUNK*CHUNK];
__device__ float g_states[(size_t)BATCH*NC*NH*HD*DS];
__device__ float g_inter[(size_t)BATCH*NC*NH*HD*DS];
__device__ float g_y[(size_t)TOK*DI];
__device__ float g_yn[(size_t)TOK*DI];

// ================= helpers =================
__device__ __forceinline__ uint32_t smem_u32(const void* p) {
    uint32_t a;
    asm("{ .reg .u64 t; cvta.to.shared.u64 t, %1; cvt.u32.u64 %0, t; }" : "=r"(a) : "l"(p));
    return a;
}
// split x0,x1 -> hi bf16x2 (rn) and lo bf16x2 (residual)
__device__ __forceinline__ void split2(float x0, float x1, uint32_t& hi, uint32_t& lo) {
    uint32_t h;
    asm("cvt.rn.bf16x2.f32 %0, %1, %2;" : "=r"(h) : "f"(x1), "f"(x0));
    float h0 = __uint_as_float(h << 16);
    float h1 = __uint_as_float(h & 0xFFFF0000u);
    float l0 = x0 - h0, l1 = x1 - h1;
    asm("cvt.rn.bf16x2.f32 %0, %1, %2;" : "=r"(lo) : "f"(l1), "f"(l0));
    hi = h;
}
#define LDMX4(r0, r1, r2, r3, addr) \
    asm volatile("ldmatrix.sync.aligned.m8n8.x4.shared.b16 {%0,%1,%2,%3}, [%4];" \
                 : "=r"(r0), "=r"(r1), "=r"(r2), "=r"(r3) : "r"(addr))
#define MMA16816(d, a, b0, b1) \
    asm volatile("mma.sync.aligned.m16n8k16.row.col.f32.bf16.bf16.f32 " \
                 "{%0,%1,%2,%3}, {%4,%5,%6,%7}, {%8,%9}, {%0,%1,%2,%3};" \
                 : "+f"(d[0]), "+f"(d[1]), "+f"(d[2]), "+f"(d[3]) \
                 : "r"(a[0]), "r"(a[1]), "r"(a[2]), "r"(a[3]), "r"(b0), "r"(b1))

// ---------------- K1/K9: split-bf16 mma.sync GEMM  C[M,N]=A[M,K]@B[N,K]^T + bias ----------------
// M%128==0, K%32==0, N guarded. 128x128x32 tile, 8 warps (4m x 2n), warp tile 32x64.
#define BM 128
#define BN 128
#define BK 32
#define LDT 40   /* padded bf16 row stride (80B) */

__global__ __launch_bounds__(256, 2) void gemm_mma(
    const float* __restrict__ A, const float* __restrict__ B,
    const float* __restrict__ bias, float* __restrict__ C,
    int M, int N, int K)
{
    __shared__ __align__(16) __nv_bfloat16 Ah[BM * LDT];
    __shared__ __align__(16) __nv_bfloat16 Al[BM * LDT];
    __shared__ __align__(16) __nv_bfloat16 Bh[BN * LDT];
    __shared__ __align__(16) __nv_bfloat16 Bl[BN * LDT];

    int tid = threadIdx.x;
    int warp = tid >> 5, lane = tid & 31;
    int wm = warp & 3, wn = warp >> 2;          // 4 m-warps x 2 n-warps
    int m0 = blockIdx.y * BM, n0 = blockIdx.x * BN;

    float acc[2][8][4];
#pragma unroll
    for (int mi = 0; mi < 2; mi++)
#pragma unroll
        for (int ni = 0; ni < 8; ni++)
#pragma unroll
            for (int e = 0; e < 4; e++) acc[mi][ni][e] = 0.f;

    // gmem load mapping: 256 threads, each 4 float4 per tile
    int lrow = tid >> 3;            // 0..31
    int lc4  = tid & 7;             // float4 column (covers 4 f32)

    uint32_t ah_b = smem_u32(Ah), al_b = smem_u32(Al);
    uint32_t bh_b = smem_u32(Bh), bl_b = smem_u32(Bl);

    // per-thread ldmatrix row/col components
    int lrow16 = lane & 15;
    int lkoff  = (lane >> 4) * 8;   // 0 or 8 elems

    const float4 z4 = make_float4(0.f, 0.f, 0.f, 0.f);

    for (int k0 = 0; k0 < K; k0 += BK) {
        // ---- load + split A tile (128 x 32 f32) ----
#pragma unroll
        for (int u = 0; u < 4; u++) {
            int r = lrow + u * 32;
            float4 v = *(const float4*)&A[(size_t)(m0 + r) * K + k0 + lc4 * 4];
            uint32_t h0, l0, h1, l1;
            split2(v.x, v.y, h0, l0);
            split2(v.z, v.w, h1, l1);
            uint32_t off = (uint32_t)(r * LDT + lc4 * 4) * 2;   // bytes
            asm volatile("st.shared.v2.b32 [%0], {%1,%2};" :: "r"(ah_b + off), "r"(h0), "r"(h1) : "memory");
            asm volatile("st.shared.v2.b32 [%0], {%1,%2};" :: "r"(al_b + off), "r"(l0), "r"(l1) : "memory");
        }
        // ---- load + split B tile (128 x 32 f32), N-guarded ----
#pragma unroll
        for (int u = 0; u < 4; u++) {
            int r = lrow + u * 32;
            float4 v = (n0 + r < N) ? *(const float4*)&B[(size_t)(n0 + r) * K + k0 + lc4 * 4] : z4;
            uint32_t h0, l0, h1, l1;
            split2(v.x, v.y, h0, l0);
            split2(v.z, v.w, h1, l1);
            uint32_t off = (uint32_t)(r * LDT + lc4 * 4) * 2;
            asm volatile("st.shared.v2.b32 [%0], {%1,%2};" :: "r"(bh_b + off), "r"(h0), "r"(h1) : "memory");
            asm volatile("st.shared.v2.b32 [%0], {%1,%2};" :: "r"(bl_b + off), "r"(l0), "r"(l1) : "memory");
        }
        __syncthreads();

        // ---- compute: 2 k16 steps ----
#pragma unroll
        for (int ks = 0; ks < BK; ks += 16) {
            uint32_t ahf[2][4], alf[2][4];
#pragma unroll
            for (int mi = 0; mi < 2; mi++) {
                uint32_t off = (uint32_t)((wm * 32 + mi * 16 + lrow16) * LDT + ks + lkoff) * 2;
                LDMX4(ahf[mi][0], ahf[mi][1], ahf[mi][2], ahf[mi][3], ah_b + off);
                LDMX4(alf[mi][0], alf[mi][1], alf[mi][2], alf[mi][3], al_b + off);
            }
#pragma unroll
            for (int nt = 0; nt < 4; nt++) {    // n16 groups
                uint32_t off = (uint32_t)((wn * 64 + nt * 16 + lrow16) * LDT + ks + lkoff) * 2;
                uint32_t h0, h1, h2, h3, l0, l1, l2, l3;
                LDMX4(h0, h1, h2, h3, bh_b + off);
                LDMX4(l0, l1, l2, l3, bl_b + off);
                // tile (nt*2): regs {r0, r2}; tile (nt*2+1): {r1, r3}
#pragma unroll
                for (int mi = 0; mi < 2; mi++) {
                    MMA16816(acc[mi][nt * 2 + 0], ahf[mi], h0, h2);
                    MMA16816(acc[mi][nt * 2 + 0], alf[mi], h0, h2);
                    MMA16816(acc[mi][nt * 2 + 0], ahf[mi], l0, l2);
                    MMA16816(acc[mi][nt * 2 + 1], ahf[mi], h1, h3);
                    MMA16816(acc[mi][nt * 2 + 1], alf[mi], h1, h3);
                    MMA16816(acc[mi][nt * 2 + 1], ahf[mi], l1, l3);
                }
            }
        }
        __syncthreads();
    }

    // ---- epilogue: c{0,1} at row, c{2,3} at row+8; cols 2*(lane&3)+{0,1} ----
    int rbase = m0 + wm * 32 + (lane >> 2);
    int cbase = n0 + wn * 64 + (lane & 3) * 2;
#pragma unroll
    for (int mi = 0; mi < 2; mi++) {
#pragma unroll
        for (int ni = 0; ni < 8; ni++) {
            int col = cbase + ni * 8;
            if (col < N) {
                float2 bb = *(const float2*)&bias[col];
                int r0 = rbase + mi * 16;
                float2 v0 = make_float2(acc[mi][ni][0] + bb.x, acc[mi][ni][1] + bb.y);
                *(float2*)&C[(size_t)r0 * N + col] = v0;
                float2 v1 = make_float2(acc[mi][ni][2] + bb.x, acc[mi][ni][3] + bb.y);
                *(float2*)&C[(size_t)(r0 + 8) * N + col] = v1;
            }
        }
    }
}

// ---------------- K2: dt softplus + per-chunk inclusive cumsum of A*dt ----------------
__global__ __launch_bounds__(256) void dt_scan_kernel(
    const float* __restrict__ dt_bias, const float* __restrict__ A_log)
{
    int blk = blockIdx.x;
    int c = blk % NC; int bh = blk / NC;
    int h = bh % NH;  int b = bh / NH;
    int t = threadIdx.x;
    int l = c * CHUNK + t;

    float x = g_zxbcdt[(size_t)(b * SEQ + l) * DIP + OFF_DT + h] + dt_bias[h];
    float sp = (x > 20.f) ? x : log1pf(expf(x));
    g_dtsp[(b * SEQ + l) * NH + h] = sp;
    float da = -expf(A_log[h]) * sp;

    __shared__ float s[CHUNK];
    s[t] = da;
    __syncthreads();
    for (int off = 1; off < CHUNK; off <<= 1) {
        float v = (t >= off) ? s[t - off] : 0.f;
        __syncthreads();
        s[t] += v;
        __syncthreads();
    }
    int base = ((b * NH + h) * NC + c) * CHUNK;
    g_dacs[base + t] = s[t];
    if (t == CHUNK - 1) g_csum[(b * NH + h) * NC + c] = s[t];
}

// ---------------- K3: causal depthwise conv4 + SiLU + scatter ----------------
__global__ __launch_bounds__(256) void conv_kernel(
    const float* __restrict__ conv_w, const float* __restrict__ conv_b)
{
    int tok = blockIdx.x;
    int ch = blockIdx.y * 256 + threadIdx.x;
    if (ch >= CONVD) return;
    int b = tok / SEQ, l = tok % SEQ;

    const float* w = conv_w + ch * 4;
    float acc = conv_b[ch];
#pragma unroll
    for (int j = 0; j < 4; j++) {
        int ls = l - 3 + j;
        if (ls >= 0)
            acc += w[j] * g_zxbcdt[(size_t)(b * SEQ + ls) * DIP + DI + ch];
    }
    float v = acc / (1.f + __expf(-acc));

    int c = l / CHUNK, t = l % CHUNK;
    if (ch < DI) {
        int h = ch >> 7, p = ch & 127;
        float dt = g_dtsp[(b * SEQ + l) * NH + h];
        g_X[(size_t)(((b * NC + c) * NH + h) * CHUNK + t) * HD + p] = v * dt;
    } else if (ch < DI + DS) {
        g_Bm[((b * NC + c) * CHUNK + t) * DS + (ch - DI)] = v;
    } else {
        g_Cm[((b * NC + c) * CHUNK + t) * DS + (ch - DI - DS)] = v;
    }
}

// ---------------- K4: G[l,s] = sum_n C[l,n] B[s,n] per (b,c) ----------------
__global__ __launch_bounds__(256) void bc_gemm_kernel()
{
    int bc = blockIdx.y;
    int tile = blockIdx.x;
    int l0 = (tile >> 2) * 64, s0 = (tile & 3) * 64;
    __shared__ float Cs[64][65];
    __shared__ float Bs[64][65];
    int tid = threadIdx.x;
    const float* Cb = g_Cm + (size_t)bc * CHUNK * DS;
    const float* Bb = g_Bm + (size_t)bc * CHUNK * DS;

#pragma unroll
    for (int u = 0; u < 4; u++) {
        int e = tid + u * 256;
        int r = e >> 4, cv = (e & 15) << 2;
        float4 vc = *(const float4*)&Cb[(l0 + r) * DS + cv];
        Cs[r][cv + 0] = vc.x; Cs[r][cv + 1] = vc.y; Cs[r][cv + 2] = vc.z; Cs[r][cv + 3] = vc.w;
        float4 vb = *(const float4*)&Bb[(s0 + r) * DS + cv];
        Bs[r][cv + 0] = vb.x; Bs[r][cv + 1] = vb.y; Bs[r][cv + 2] = vb.z; Bs[r][cv + 3] = vb.w;
    }
    __syncthreads();

    int sq = tid & 15, lq = tid >> 4;
    float acc[4][4];
#pragma unroll
    for (int i = 0; i < 4; i++)
#pragma unroll
        for (int j = 0; j < 4; j++) acc[i][j] = 0.f;

#pragma unroll 8
    for (int n = 0; n < 64; n++) {
        float a[4], bb[4];
#pragma unroll
        for (int i = 0; i < 4; i++) a[i] = Cs[lq * 4 + i][n];
#pragma unroll
        for (int j = 0; j < 4; j++) bb[j] = Bs[sq * 4 + j][n];
#pragma unroll
        for (int i = 0; i < 4; i++)
#pragma unroll
            for (int j = 0; j < 4; j++) acc[i][j] = fmaf(a[i], bb[j], acc[i][j]);
    }
    float* Gout = g_G + (size_t)bc * CHUNK * CHUNK;
#pragma unroll
    for (int i = 0; i < 4; i++) {
        float4 v = make_float4(acc[i][0], acc[i][1], acc[i][2], acc[i][3]);
        *(float4*)&Gout[(l0 + lq * 4 + i) * CHUNK + s0 + sq * 4] = v;
    }
}

// ---------------- K5: Y_diag = (G .* L) @ X per (b,c,h) ----------------
__global__ __launch_bounds__(512) void ydiag_kernel()
{
    int blk = blockIdx.x;
    int h = blk % NH; int bc = blk / NH;
    int c = bc % NC;  int b = bc / NC;

    __shared__ __align__(16) float Ms[16][256];
    __shared__ __align__(16) float Xs[16][128];
    __shared__ float acs[CHUNK];
    int tid = threadIdx.x;
    if (tid < 256) acs[tid] = g_dacs[((b * NH + h) * NC + c) * CHUNK + tid];
    __syncthreads();

    const float* Gb = g_G + (size_t)bc * CHUNK * CHUNK;
    const float* Xb = g_X + (size_t)blk * CHUNK * HD;

    float acc[8][8];
#pragma unroll
    for (int i = 0; i < 8; i++)
#pragma unroll
        for (int j = 0; j < 8; j++) acc[i][j] = 0.f;

    int tx = tid & 15, ty = tid >> 4;

    for (int s0 = 0; s0 < CHUNK; s0 += 16) {
        {
            int r = tid >> 5, cv = (tid & 31) << 2;
            float4 v = *(const float4*)&Xb[(s0 + r) * HD + cv];
            *(float4*)&Xs[r][cv] = v;
        }
#pragma unroll
        for (int u = 0; u < 2; u++) {
            int e = tid * 2 + u;
            int r = e >> 2;
            int sv = (e & 3) << 2;
            float4 g4 = *(const float4*)&Gb[r * CHUNK + s0 + sv];
            float al = acs[r];
            int sg = s0 + sv;
            Ms[sv + 0][r] = (sg + 0 <= r) ? g4.x * __expf(al - acs[sg + 0]) : 0.f;
            Ms[sv + 1][r] = (sg + 1 <= r) ? g4.y * __expf(al - acs[sg + 1]) : 0.f;
            Ms[sv + 2][r] = (sg + 2 <= r) ? g4.z * __expf(al - acs[sg + 2]) : 0.f;
            Ms[sv + 3][r] = (sg + 3 <= r) ? g4.w * __expf(al - acs[sg + 3]) : 0.f;
        }
        __syncthreads();
#pragma unroll
        for (int kk = 0; kk < 16; kk++) {
            float a[8], bb[8];
            *(float4*)&a[0] = *(float4*)&Ms[kk][ty * 8];
            *(float4*)&a[4] = *(float4*)&Ms[kk][ty * 8 + 4];
            *(float4*)&bb[0] = *(float4*)&Xs[kk][tx * 8];
            *(float4*)&bb[4] = *(float4*)&Xs[kk][tx * 8 + 4];
#pragma unroll
            for (int i = 0; i < 8; i++)
#pragma unroll
                for (int j = 0; j < 8; j++)
                    acc[i][j] = fmaf(a[i], bb[j], acc[i][j]);
        }
        __syncthreads();
    }

#pragma unroll
    for (int i = 0; i < 8; i++) {
        int l = ty * 8 + i;
        float* out = g_y + (size_t)(b * SEQ + c * CHUNK + l) * DI + h * HD;
#pragma unroll
        for (int j = 0; j < 8; j += 4) {
            float4 v = make_float4(acc[i][j], acc[i][j + 1], acc[i][j + 2], acc[i][j + 3]);
            *(float4*)&out[tx * 8 + j] = v;
        }
    }
}

// ---------------- K5b: local states[p,n] = sum_l X[l,p]*decay[l]*B[l,n] ----------------
__global__ __launch_bounds__(256) void states_kernel()
{
    int blk = blockIdx.x;
    int h = blk % NH; int bc = blk / NH;
    int c = bc % NC;  int b = bc / NC;

    __shared__ __align__(16) float Xs[32][128];
    __shared__ __align__(16) float Bs[32][64];
    __shared__ float ws[32];
    __shared__ float acs[CHUNK];
    int tid = threadIdx.x;
    if (tid < 256) acs[tid] = g_dacs[((b * NH + h) * NC + c) * CHUNK + tid];
    __syncthreads();
    float alast = acs[CHUNK - 1];

    const float* Xb = g_X + (size_t)blk * CHUNK * HD;
    const float* Bb = g_Bm + (size_t)bc * CHUNK * DS;

    int nq = tid & 7, pq = tid >> 3;
    float acc[4][8];
#pragma unroll
    for (int i = 0; i < 4; i++)
#pragma unroll
        for (int j = 0; j < 8; j++) acc[i][j] = 0.f;

    for (int l0 = 0; l0 < CHUNK; l0 += 32) {
#pragma unroll
        for (int u = 0; u < 4; u++) {
            int e = tid + u * 256;
            int r = e >> 5, cv = (e & 31) << 2;
            *(float4*)&Xs[r][cv] = *(const float4*)&Xb[(l0 + r) * HD + cv];
        }
#pragma unroll
        for (int u = 0; u < 2; u++) {
            int e = tid + u * 256;
            int r = e >> 4, cv = (e & 15) << 2;
            *(float4*)&Bs[r][cv] = *(const float4*)&Bb[(l0 + r) * DS + cv];
        }
        if (tid < 32) ws[tid] = __expf(alast - acs[l0 + tid]);
        __syncthreads();
#pragma unroll
        for (int lt = 0; lt < 32; lt++) {
            float w = ws[lt];
            float a[4];
#pragma unroll
            for (int i = 0; i < 4; i++) a[i] = Xs[lt][pq * 4 + i] * w;
            float bb[8];
            *(float4*)&bb[0] = *(float4*)&Bs[lt][nq * 8];
            *(float4*)&bb[4] = *(float4*)&Bs[lt][nq * 8 + 4];
#pragma unroll
            for (int i = 0; i < 4; i++)
#pragma unroll
                for (int j = 0; j < 8; j++)
                    acc[i][j] = fmaf(a[i], bb[j], acc[i][j]);
        }
        __syncthreads();
    }
    float* So = g_states + (size_t)blk * HD * DS;
#pragma unroll
    for (int i = 0; i < 4; i++) {
#pragma unroll
        for (int j = 0; j < 8; j += 4) {
            float4 v = make_float4(acc[i][j], acc[i][j + 1], acc[i][j + 2], acc[i][j + 3]);
            *(float4*)&So[(pq * 4 + i) * DS + nq * 8 + j] = v;
        }
    }
}

// ---------------- K6: inter-chunk scan ----------------
__global__ __launch_bounds__(256) void scan_kernel()
{
    int bh = blockIdx.x;
    int b = bh / NH, h = bh % NH;
    int tid = threadIdx.x;
    float S[32];
#pragma unroll
    for (int k = 0; k < 32; k++) S[k] = 0.f;
    for (int c = 0; c < NC; c++) {
        float dec = __expf(g_csum[bh * NC + c]);
        size_t base = (size_t)((b * NC + c) * NH + h) * HD * DS;
#pragma unroll
        for (int k = 0; k < 32; k++) {
            int e = tid + k * 256;
            g_inter[base + e] = S[k];
            S[k] = S[k] * dec + g_states[base + e];
        }
    }
}

// ---------------- K7: Y_off + combine + silu(z) gate ----------------
__global__ __launch_bounds__(256) void yoff_kernel()
{
    int blk = blockIdx.x;
    int h = blk % NH; int bc = blk / NH;
    int c = bc % NC;  int b = bc / NC;

    __shared__ float Is[HD][DS + 1];
    __shared__ float Cs[64][DS + 1];
    __shared__ float acs[CHUNK];
    int tid = threadIdx.x;
    if (tid < 256) acs[tid] = g_dacs[((b * NH + h) * NC + c) * CHUNK + tid];

    const float* Ib = g_inter + (size_t)blk * HD * DS;
#pragma unroll
    for (int u = 0; u < 8; u++) {
        int e = tid + u * 256;
        int r = e >> 4, cv = (e & 15) << 2;
        float4 v = *(const float4*)&Ib[r * DS + cv];
        Is[r][cv + 0] = v.x; Is[r][cv + 1] = v.y; Is[r][cv + 2] = v.z; Is[r][cv + 3] = v.w;
    }

    int tq = tid & 7, pq = tid >> 3;
    const float* Cb = g_Cm + (size_t)bc * CHUNK * DS;

    for (int tg = 0; tg < 4; tg++) {
        __syncthreads();
#pragma unroll
        for (int u = 0; u < 4; u++) {
            int e = tid + u * 256;
            int r = e >> 4, cv = (e & 15) << 2;
            float4 v = *(const float4*)&Cb[(tg * 64 + r) * DS + cv];
            Cs[r][cv + 0] = v.x; Cs[r][cv + 1] = v.y; Cs[r][cv + 2] = v.z; Cs[r][cv + 3] = v.w;
        }
        __syncthreads();

        float acc[8][4];
#pragma unroll
        for (int k = 0; k < 8; k++)
#pragma unroll
            for (int i = 0; i < 4; i++) acc[k][i] = 0.f;

#pragma unroll 4
        for (int n = 0; n < DS; n++) {
            float iv[4];
#pragma unroll
            for (int i = 0; i < 4; i++) iv[i] = Is[pq * 4 + i][n];
#pragma unroll
            for (int k = 0; k < 8; k++) {
                float cv = Cs[k * 8 + tq][n];
#pragma unroll
                for (int i = 0; i < 4; i++)
                    acc[k][i] = fmaf(cv, iv[i], acc[k][i]);
            }
        }

#pragma unroll
        for (int k = 0; k < 8; k++) {
            int t = tg * 64 + k * 8 + tq;
            float ea = __expf(acs[t]);
            int gl = c * CHUNK + t;
            size_t yidx = (size_t)(b * SEQ + gl) * DI + h * HD + pq * 4;
            size_t zidx = (size_t)(b * SEQ + gl) * DIP + h * HD + pq * 4;
            float4 yd = *(float4*)&g_y[yidx];
            float4 z  = *(const float4*)&g_zxbcdt[zidx];
            float4 o;
            o.x = (yd.x + ea * acc[k][0]) * z.x / (1.f + __expf(-z.x));
            o.y = (yd.y + ea * acc[k][1]) * z.y / (1.f + __expf(-z.y));
            o.z = (yd.z + ea * acc[k][2]) * z.z / (1.f + __expf(-z.z));
            o.w = (yd.w + ea * acc[k][3]) * z.w / (1.f + __expf(-z.w));
            *(float4*)&g_y[yidx] = o;
        }
    }
}

// ---------------- K8: layernorm over 4096 ----------------
__global__ __launch_bounds__(256) void ln_kernel(
    const float* __restrict__ ln_w, const float* __restrict__ ln_b)
{
    int tok = blockIdx.x;
    const float* y = g_y + (size_t)tok * DI;
    float* o = g_yn + (size_t)tok * DI;
    int tid = threadIdx.x;

    float v[16];
    float s = 0.f, ss = 0.f;
#pragma unroll
    for (int u = 0; u < 4; u++) {
        float4 x = *(const float4*)&y[tid * 4 + u * 1024];
        v[u * 4 + 0] = x.x; v[u * 4 + 1] = x.y; v[u * 4 + 2] = x.z; v[u * 4 + 3] = x.w;
        s += x.x + x.y + x.z + x.w;
        ss += x.x * x.x + x.y * x.y + x.z * x.z + x.w * x.w;
    }
#pragma unroll
    for (int off = 16; off; off >>= 1) {
        s  += __shfl_xor_sync(0xFFFFFFFFu, s, off);
        ss += __shfl_xor_sync(0xFFFFFFFFu, ss, off);
    }
    __shared__ float rs[8], rss[8];
    int warp = tid >> 5, lane = tid & 31;
    if (lane == 0) { rs[warp] = s; rss[warp] = ss; }
    __syncthreads();
    s = 0.f; ss = 0.f;
#pragma unroll
    for (int w = 0; w < 8; w++) { s += rs[w]; ss += rss[w]; }
    float mu = s * (1.f / DI);
    float var = ss * (1.f / DI) - mu * mu;
    float rstd = rsqrtf(var + 1e-5f);
#pragma unroll
    for (int u = 0; u < 4; u++) {
        int idx = tid * 4 + u * 1024;
        float4 w4 = *(const float4*)&ln_w[idx];
        float4 b4 = *(const float4*)&ln_b[idx];
        float4 ov;
        ov.x = (v[u * 4 + 0] - mu) * rstd * w4.x + b4.x;
        ov.y = (v[u * 4 + 1] - mu) * rstd * w4.y + b4.y;
        ov.z = (v[u * 4 + 2] - mu) * rstd * w4.z + b4.z;
        ov.w = (v[u * 4 + 3] - mu) * rstd * w4.w + b4.w;
        *(float4*)&o[idx] = ov;
    }
}

// ---------------- launch ----------------
extern "C" void kernel_launch(void* const* d_in, const int* in_sizes, int n_in,
                              void* d_out, int out_size)
{
    const float* u          = (const float*)d_in[0];
    const float* in_proj_w  = (const float*)d_in[1];
    const float* in_proj_b  = (const float*)d_in[2];
    const float* conv_w     = (const float*)d_in[3];
    const float* conv_b     = (const float*)d_in[4];
    const float* dt_bias    = (const float*)d_in[5];
    const float* A_log      = (const float*)d_in[6];
    const float* ln_w       = (const float*)d_in[7];
    const float* ln_b       = (const float*)d_in[8];
    const float* out_proj_w = (const float*)d_in[9];
    const float* out_proj_b = (const float*)d_in[10];
    float* out = (float*)d_out;

    float* zx; cudaGetSymbolAddress((void**)&zx, g_zxbcdt);
    float* yn; cudaGetSymbolAddress((void**)&yn, g_yn);

    // K1: in_proj GEMM (8192 x 8352 x 2048), split-bf16 mma.sync
    gemm_mma<<<dim3((DIP + BN - 1) / BN, TOK / BM), 256>>>(
        u, in_proj_w, in_proj_b, zx, TOK, DIP, DM);
    // K2: dt softplus + per-chunk cumsum
    dt_scan_kernel<<<BATCH * NH * NC, CHUNK>>>(dt_bias, A_log);
    // K3: conv + silu + scatter
    conv_kernel<<<dim3(TOK, (CONVD + 255) / 256), 256>>>(conv_w, conv_b);
    // K4: G = C B^T per (b,c)
    bc_gemm_kernel<<<dim3(16, BATCH * NC), 256>>>();
    // K5: Y_diag
    ydiag_kernel<<<BATCH * NC * NH, 512>>>();
    // K5b: local chunk states
    states_kernel<<<BATCH * NC * NH, 256>>>();
    // K6: inter-chunk scan
    scan_kernel<<<BATCH * NH, 256>>>();
    // K7: Y_off + gate
    yoff_kernel<<<BATCH * NC * NH, 256>>>();
    // K8: layernorm
    ln_kernel<<<TOK, 256>>>(ln_w, ln_b);
    // K9: out_proj GEMM (8192 x 2048 x 4096), split-bf16 mma.sync
    gemm_mma<<<dim3(DM / BN, TOK / BM), 256>>>(
        yn, out_proj_w, out_proj_b, out, TOK, DM, DI);
}